// round 12
// baseline (speedup 1.0000x reference)
#include <cuda_runtime.h>
#include <cuda_bf16.h>
#include <cuda_pipeline.h>
#include <mma.h>
#include <math.h>
#include <stdint.h>

using namespace nvcuda;

#define NTOT 4096
#define NSUP 1024
#define DIM  1024
#define MAXD 1024
#define CAP  192
#define NITER 96
#define SBLK 32
#define GSKW 40                                    // smem stride (bf16), 80B

// ---------------- device scratch (allocation-free: __device__ globals) ------
__device__ float g_X [(size_t)NTOT * DIM];          // 16 MB fp32 inputs
__device__ __nv_bfloat16 g_Xh[(size_t)NTOT * DIM];  // 8 MB bf16
__device__ float g_G [(size_t)NTOT * NTOT];         // 64 MB Gram (bf16-accurate)
__device__ float g_sq[NTOT];
__device__ int   g_cand[(size_t)NTOT * CAP];        // 3 MB candidate sets
__device__ int   g_candn[NTOT];
__device__ __align__(16) int g_top4[NTOT * 4];
__device__ int   g_adj[(size_t)NTOT * MAXD];
__device__ int   g_deg[NTOT];
__device__ float g_Wv[(size_t)NTOT * MAXD];
__device__ float g_D[NTOT];
__device__ int2  g_edge[(size_t)NTOT * MAXD];
__device__ float g_y[NTOT * 2];
__device__ float g_xbuf[2][NTOT * 2];
__device__ unsigned g_count;
__device__ volatile unsigned g_gen;

// ---------------- stage 0: concat + bf16 copy --------------------------------
__global__ void k_concat(const float* __restrict__ lab, const float* __restrict__ unlab) {
    size_t nl  = (size_t)NSUP * DIM;
    size_t tot = (size_t)NTOT * DIM;
    for (size_t idx = blockIdx.x * (size_t)blockDim.x + threadIdx.x; idx < tot;
         idx += gridDim.x * (size_t)blockDim.x) {
        float v = (idx < nl) ? lab[idx] : unlab[idx - nl];
        g_X[idx] = v;
        g_Xh[idx] = __float2bfloat16_rn(v);
    }
}

// ---------------- stage 1: row squared norms ---------------------------------
__global__ void k_sq() {
    int i = blockIdx.x, tid = threadIdx.x;
    __shared__ float red[256];
    const float* r = g_X + (size_t)i * DIM;
    float s = 0.f;
    for (int k = tid; k < DIM; k += 256) { float v = r[k]; s += v * v; }
    red[tid] = s; __syncthreads();
    for (int st = 128; st > 0; st >>= 1) {
        if (tid < st) red[tid] += red[tid + st];
        __syncthreads();
    }
    if (tid == 0) g_sq[i] = red[0];
}

// ---------------- stage 2: single-term bf16 wmma GEMM, K=32 pipeline ---------
__global__ void __launch_bounds__(256, 2) k_gemm() {
    int bi = blockIdx.y, bj = blockIdx.x;
    if (bj < bi) return;
    __shared__ __align__(16) __nv_bfloat16 S[2][2][128 * GSKW];   // 40 KB

    int tid = threadIdx.x;
    int wid = tid >> 5;
    int rA = bi * 128, rB = bj * 128;
    int mbase = (wid >> 2) * 64, nbase = (wid & 3) * 32;

    wmma::fragment<wmma::accumulator, 16, 16, 16, float> acc[4][2];
    #pragma unroll
    for (int u = 0; u < 4; u++)
        #pragma unroll
        for (int v = 0; v < 2; v++) wmma::fill_fragment(acc[u][v], 0.0f);

    int r0 = tid >> 2,          p0 = (tid & 3) * 8;          // chunk 0
    int r1 = (tid + 256) >> 2,  p1 = ((tid + 256) & 3) * 8;  // chunk 1

    const int NKT = DIM / 32;                  // 32 stages

    // prologue: stage 0
    __pipeline_memcpy_async(&S[0][0][r0 * GSKW + p0], &g_Xh[(size_t)(rA + r0) * DIM + p0], 16);
    __pipeline_memcpy_async(&S[0][0][r1 * GSKW + p1], &g_Xh[(size_t)(rA + r1) * DIM + p1], 16);
    __pipeline_memcpy_async(&S[0][1][r0 * GSKW + p0], &g_Xh[(size_t)(rB + r0) * DIM + p0], 16);
    __pipeline_memcpy_async(&S[0][1][r1 * GSKW + p1], &g_Xh[(size_t)(rB + r1) * DIM + p1], 16);
    __pipeline_commit();

    for (int kt = 0; kt < NKT; kt++) {
        __pipeline_wait_prior(0);
        __syncthreads();
        if (kt + 1 < NKT) {
            int st = (kt + 1) & 1;
            size_t ko = (size_t)(kt + 1) * 32;
            __pipeline_memcpy_async(&S[st][0][r0 * GSKW + p0], &g_Xh[(size_t)(rA + r0) * DIM + ko + p0], 16);
            __pipeline_memcpy_async(&S[st][0][r1 * GSKW + p1], &g_Xh[(size_t)(rA + r1) * DIM + ko + p1], 16);
            __pipeline_memcpy_async(&S[st][1][r0 * GSKW + p0], &g_Xh[(size_t)(rB + r0) * DIM + ko + p0], 16);
            __pipeline_memcpy_async(&S[st][1][r1 * GSKW + p1], &g_Xh[(size_t)(rB + r1) * DIM + ko + p1], 16);
            __pipeline_commit();
        }

        int st = kt & 1;
        #pragma unroll
        for (int kk = 0; kk < 32; kk += 16) {
            wmma::fragment<wmma::matrix_b, 16, 16, 16, __nv_bfloat16, wmma::col_major> bh[2];
            #pragma unroll
            for (int v = 0; v < 2; v++)
                wmma::load_matrix_sync(bh[v], &S[st][1][(nbase + v * 16) * GSKW + kk], GSKW);
            #pragma unroll
            for (int u = 0; u < 4; u++) {
                wmma::fragment<wmma::matrix_a, 16, 16, 16, __nv_bfloat16, wmma::row_major> ah;
                wmma::load_matrix_sync(ah, &S[st][0][(mbase + u * 16) * GSKW + kk], GSKW);
                #pragma unroll
                for (int v = 0; v < 2; v++)
                    wmma::mma_sync(acc[u][v], ah, bh[v], acc[u][v]);
            }
        }
    }

    #pragma unroll
    for (int u = 0; u < 4; u++)
        #pragma unroll
        for (int v = 0; v < 2; v++) {
            int gi = rA + mbase + u * 16;
            int gj = rB + nbase + v * 16;
            wmma::store_matrix_sync(&g_G[(size_t)gi * NTOT + gj], acc[u][v],
                                    NTOT, wmma::mem_row_major);
            if (bi != bj)
                wmma::store_matrix_sync(&g_G[(size_t)gj * NTOT + gi], acc[u][v],
                                        NTOT, wmma::mem_col_major);
        }
}

// ---------------- stage 3: threshold-collect candidate sets ------------------
// pass1: block-exact 4th-smallest approx dist; pass2: collect all within MARGIN
__global__ void k_topk() {
    int i = blockIdx.x, tid = threadIdx.x;
    int lane = tid & 31, warp = tid >> 5;
    __shared__ float swv[32];
    __shared__ float s_T;
    __shared__ int   s_cnt;
    __shared__ int   s_list[CAP];

    float sqi = g_sq[i];
    const float4* Grow = (const float4*)(g_G + (size_t)i * NTOT);

    float4 gg[4];
    #pragma unroll
    for (int t = 0; t < 4; t++) gg[t] = Grow[tid + t * 256];

    float bd[4]  = { INFINITY, INFINITY, INFINITY, INFINITY };
    int   bix[4] = { 0x7fffffff, 0x7fffffff, 0x7fffffff, 0x7fffffff };

    #pragma unroll
    for (int t = 0; t < 4; t++) {
        int j4 = tid + t * 256;
        float gv[4] = { gg[t].x, gg[t].y, gg[t].z, gg[t].w };
        #pragma unroll
        for (int e = 0; e < 4; e++) {
            int j = j4 * 4 + e;
            if (j == i) continue;
            float dv = sqi + g_sq[j] - 2.0f * gv[e];
            if (dv < bd[3]) {
                bd[3] = dv; bix[3] = j;
                #pragma unroll
                for (int q = 3; q > 0; q--) {
                    if (bd[q] < bd[q - 1]) {
                        float td = bd[q]; bd[q] = bd[q - 1]; bd[q - 1] = td;
                        int ti = bix[q]; bix[q] = bix[q - 1]; bix[q - 1] = ti;
                    } else break;
                }
            }
        }
    }

    // per-warp 4 ascending minima (bitmask rounds, static indexing)
    unsigned used = 0;
    for (int r = 0; r < 4; r++) {
        float cv = INFINITY; int ci = 0x7fffffff; int cq = -1;
        #pragma unroll
        for (int q = 0; q < 4; q++) {
            if (!((used >> q) & 1u)) {
                if (bd[q] < cv || (bd[q] == cv && bix[q] < ci)) {
                    cv = bd[q]; ci = bix[q]; cq = q;
                }
            }
        }
        float mv = cv; int mi = ci;
        #pragma unroll
        for (int o = 16; o > 0; o >>= 1) {
            float ov = __shfl_xor_sync(0xffffffffu, cv, o);
            int   oi = __shfl_xor_sync(0xffffffffu, ci, o);
            if (ov < cv || (ov == cv && oi < ci)) { cv = ov; ci = oi; }
        }
        if (cq >= 0 && mi == ci && mv == cv) used |= (1u << cq);
        if (lane == 0) swv[warp * 4 + r] = cv;
    }
    __syncthreads();

    if (tid == 0) {
        int head[8] = {0, 0, 0, 0, 0, 0, 0, 0};
        float v4 = INFINITY;
        for (int r = 0; r < 4; r++) {
            float best = INFINITY; int bw = 0;
            for (int w = 0; w < 8; w++) {
                if (head[w] < 4) {
                    float v = swv[w * 4 + head[w]];
                    if (v < best) { best = v; bw = w; }
                }
            }
            head[bw]++;
            v4 = best;
        }
        s_T = v4 + 0.75f;                       // ~7.5 sigma of bf16 noise
        s_cnt = 0;
    }
    __syncthreads();
    float T = s_T;

    #pragma unroll
    for (int t = 0; t < 4; t++) {
        int j4 = tid + t * 256;
        float gv[4] = { gg[t].x, gg[t].y, gg[t].z, gg[t].w };
        #pragma unroll
        for (int e = 0; e < 4; e++) {
            int j = j4 * 4 + e;
            if (j == i) continue;
            float dv = sqi + g_sq[j] - 2.0f * gv[e];
            if (dv <= T) {
                int s = atomicAdd(&s_cnt, 1);
                if (s < CAP) s_list[s] = j;
            }
        }
    }
    __syncthreads();
    int cnt = s_cnt < CAP ? s_cnt : CAP;
    if (tid == 0) g_candn[i] = cnt;
    for (int s = tid; s < cnt; s += 256) g_cand[(size_t)i * CAP + s] = s_list[s];
}

// ---------------- stage 3b: fp64 refine candidates -> exact top-4 ------------
__global__ void __launch_bounds__(256) k_refine() {
    int i = blockIdx.x;
    int warp = threadIdx.x >> 5, lane = threadIdx.x & 31;
    int M = g_candn[i];
    __shared__ double dd[CAP];
    __shared__ int    cid[CAP];

    const float* xi = g_X + (size_t)i * DIM;
    for (int c = warp; c < M; c += 8) {
        int j = g_cand[(size_t)i * CAP + c];
        const float* xj = g_X + (size_t)j * DIM;
        double s = 0.0;
        for (int k = lane; k < DIM; k += 32) {
            double d = (double)xi[k] - (double)xj[k];
            s += d * d;
        }
        #pragma unroll
        for (int o = 16; o > 0; o >>= 1) s += __shfl_down_sync(0xffffffffu, s, o);
        if (lane == 0) { dd[c] = s; cid[c] = j; }
    }
    __syncthreads();
    if (threadIdx.x == 0) {
        for (int r = 0; r < 4; r++) {
            int best = -1;
            for (int c = 0; c < M; c++) {
                if (best < 0 || dd[c] < dd[best] ||
                    (dd[c] == dd[best] && cid[c] < cid[best])) best = c;
            }
            g_top4[i * 4 + r] = cid[best];
            dd[best] = 1e300;
        }
    }
}

// ---------------- stage 4: deterministic symmetric adjacency -----------------
__global__ void k_adj() {
    int i = blockIdx.x, tid = threadIdx.x;          // 128 threads
    __shared__ int myt[4];
    __shared__ int counts[128];
    __shared__ int offs[128];
    if (tid < 4) myt[tid] = g_top4[i * 4 + tid];
    __syncthreads();
    int t0 = myt[0], t1 = myt[1], t2 = myt[2], t3 = myt[3];

    int local[32]; int cnt = 0;
    int j0 = tid * 32;
    for (int q = 0; q < 32; q++) {
        int j = j0 + q;
        int4 tj = *(const int4*)&g_top4[j * 4];
        bool rev = (tj.x == i) | (tj.y == i) | (tj.z == i) | (tj.w == i);
        if (rev && j != t0 && j != t1 && j != t2 && j != t3) local[cnt++] = j;
    }
    counts[tid] = cnt;
    __syncthreads();
    if (tid == 0) {
        int s = 0;
        for (int k = 0; k < 128; k++) { offs[k] = s; s += counts[k]; }
        int dg = 4 + s;
        g_deg[i] = dg > MAXD ? MAXD : dg;
    }
    __syncthreads();
    int base = 4 + offs[tid];
    for (int q = 0; q < cnt; q++)
        if (base + q < MAXD) g_adj[(size_t)i * MAXD + base + q] = local[q];
    if (tid < 4) g_adj[(size_t)i * MAXD + tid] = myt[tid];
}

// ---------------- stage 5: edge weights (direct fp32 dots) + D + y ----------
__global__ void __launch_bounds__(256) k_weights(const int* __restrict__ tgt) {
    int i = blockIdx.x;
    int tid = threadIdx.x;
    int warp = tid >> 5, lane = tid & 31;
    __shared__ float wv[MAXD];
    __shared__ float4 xs[256];

    xs[tid] = ((const float4*)(g_X + (size_t)i * DIM))[tid];
    __syncthreads();

    int dg = g_deg[i];
    for (int l = warp; l < dg; l += 8) {
        int j = g_adj[(size_t)i * MAXD + l];
        const float4* xj = (const float4*)(g_X + (size_t)j * DIM);
        float s = 0.f;
        for (int k = lane; k < 256; k += 32) {
            float4 a = xs[k], b = xj[k];
            float d0 = a.x - b.x, d1 = a.y - b.y, d2 = a.z - b.z, d3 = a.w - b.w;
            s += d0 * d0 + d1 * d1 + d2 * d2 + d3 * d3;
        }
        #pragma unroll
        for (int o = 16; o > 0; o >>= 1) s += __shfl_down_sync(0xffffffffu, s, o);
        if (lane == 0) wv[l] = expf(-0.5f * (s * (1.0f / 1024.0f)));
    }
    __syncthreads();
    if (tid == 0) {
        float s = 0.f;
        for (int l = 0; l < dg; l++) s += wv[l];
        g_D[i] = s;
        float y0 = 0.f, y1 = 0.f;
        if (i < NSUP) {
            int t = tgt[i];
            y0 = (t == 0) ? 1.f : 0.f;
            y1 = (t == 1) ? 1.f : 0.f;
        }
        g_y[2 * i] = y0;
        g_y[2 * i + 1] = y1;
    }
    for (int l = tid; l < dg; l += 256) g_Wv[(size_t)i * MAXD + l] = wv[l];
}

// ---------------- stage 6: packed edges, alpha * (d_i * W * d_j) -------------
__global__ void k_scale() {
    int i = blockIdx.x * blockDim.x + threadIdx.x;
    if (i >= NTOT) return;
    const float EPSF = 2.220446049250313e-16f;
    int dg = g_deg[i];
    float ri = sqrtf(1.0f / (g_D[i] + EPSF));
    for (int l = 0; l < dg; l++) {
        int j = g_adj[(size_t)i * MAXD + l];
        float rj = sqrtf(1.0f / (g_D[j] + EPSF));
        float sv = 0.99f * ((ri * g_Wv[(size_t)i * MAXD + l]) * rj);
        g_edge[(size_t)i * MAXD + l] = make_int2(j, __float_as_int(sv));
    }
}

// ---------------- grid barrier (writer-only fence) ----------------------------
__device__ __forceinline__ void gridbar(bool writer) {
    if (writer) __threadfence();
    __syncthreads();
    if (threadIdx.x == 0) {
        unsigned my = g_gen;
        if (atomicAdd(&g_count, 1) == SBLK - 1) {
            g_count = 0;
            __threadfence();
            g_gen = my + 1;
        } else {
            while (g_gen == my) { __nanosleep(32); }
        }
        __threadfence();
    }
    __syncthreads();
}

// ---------------- stage 8: Chebyshev solve, 32 CTAs, 8 lanes per row ---------
__global__ void __launch_bounds__(1024, 1) k_solve(float* __restrict__ out) {
    unsigned gtid = blockIdx.x * 1024u + threadIdx.x;
    int row = gtid >> 3;
    int q8  = gtid & 7;
    bool writer = (q8 == 0);

    const float theta = 1.0f, delta = 0.99f;
    const float sigma = theta / delta;
    float rho_prev = delta / theta;

    float b0 = g_y[2 * row], b1 = g_y[2 * row + 1];
    float d0 = b0, d1 = b1;
    float x0 = b0, x1 = b1;
    int dg = g_deg[row];
    const int2* ep = g_edge + (size_t)row * MAXD;

    if (writer)
        __stcg((float2*)&g_xbuf[0][2 * row], make_float2(x0, x1));
    gridbar(writer);
    int p = 0;

    for (int it = 1; it < NITER; ++it) {
        float s0 = 0.f, s1 = 0.f;
        for (int l = q8; l < dg; l += 8) {
            int2 e = __ldg(&ep[l]);
            float w = __int_as_float(e.y);
            float2 xj = __ldcg((const float2*)&g_xbuf[p][2 * e.x]);
            s0 += w * xj.x;
            s1 += w * xj.y;
        }
        s0 += __shfl_down_sync(0xffffffffu, s0, 4, 8);
        s1 += __shfl_down_sync(0xffffffffu, s1, 4, 8);
        s0 += __shfl_down_sync(0xffffffffu, s0, 2, 8);
        s1 += __shfl_down_sync(0xffffffffu, s1, 2, 8);
        s0 += __shfl_down_sync(0xffffffffu, s0, 1, 8);
        s1 += __shfl_down_sync(0xffffffffu, s1, 1, 8);

        float rho = 1.0f / (2.0f * sigma - rho_prev);
        float c1 = rho * rho_prev, c2 = 2.0f * rho / delta;
        if (writer) {
            float rr0 = b0 - x0 + s0;
            float rr1 = b1 - x1 + s1;
            d0 = c1 * d0 + c2 * rr0;
            d1 = c1 * d1 + c2 * rr1;
            x0 += d0;
            x1 += d1;
            if (it != NITER - 1)
                __stcg((float2*)&g_xbuf[1 - p][2 * row], make_float2(x0, x1));
        }
        rho_prev = rho;
        if (it != NITER - 1) {
            gridbar(writer);
            p ^= 1;
        }
    }

    if (writer && row >= NSUP) {
        out[2 * (row - NSUP)]     = x0;
        out[2 * (row - NSUP) + 1] = x1;
    }
}

// ---------------- launch ------------------------------------------------------
extern "C" void kernel_launch(void* const* d_in, const int* in_sizes, int n_in,
                              void* d_out, int out_size) {
    const float* lab   = (const float*)d_in[0];
    const int*   tgt   = (const int*)d_in[1];
    const float* unlab = (const float*)d_in[2];
    float* out = (float*)d_out;

    k_concat<<<2048, 256>>>(lab, unlab);
    k_sq<<<NTOT, 256>>>();
    dim3 gg(32, 32);
    k_gemm<<<gg, 256>>>();
    k_topk<<<NTOT, 256>>>();
    k_refine<<<NTOT, 256>>>();
    k_adj<<<NTOT, 128>>>();
    k_weights<<<NTOT, 256>>>(tgt);
    k_scale<<<(NTOT + 255) / 256, 256>>>();
    k_solve<<<SBLK, 1024>>>(out);
}

// round 13
// speedup vs baseline: 1.5493x; 1.5493x over previous
#include <cuda_runtime.h>
#include <cuda_bf16.h>
#include <cuda_pipeline.h>
#include <mma.h>
#include <math.h>
#include <stdint.h>

using namespace nvcuda;

#define NTOT 4096
#define NSUP 1024
#define DIM  1024
#define MAXD 1024
#define CAP  192
#define NITER 96
#define SBLK 32
#define GSKW 40                                    // smem stride (bf16), 80B

// ---------------- device scratch (allocation-free: __device__ globals) ------
__device__ float g_X [(size_t)NTOT * DIM];          // 16 MB fp32 inputs
__device__ __nv_bfloat16 g_Xh[(size_t)NTOT * DIM];  // 8 MB bf16
__device__ float g_G [(size_t)NTOT * NTOT];         // 64 MB Gram (bf16-accurate)
__device__ float g_sq[NTOT];
__device__ int   g_cand[(size_t)NTOT * CAP];        // 3 MB candidate sets
__device__ int   g_candn[NTOT];
__device__ __align__(16) int g_top4[NTOT * 4];
__device__ float g_adist[NTOT * 4];                 // exact normalized dist of top4
__device__ int   g_adj[(size_t)NTOT * MAXD];
__device__ float g_adjd[(size_t)NTOT * MAXD];       // per-edge exact dist
__device__ int   g_deg[NTOT];
__device__ float g_Wv[(size_t)NTOT * MAXD];
__device__ float g_D[NTOT];
__device__ int2  g_edge[(size_t)NTOT * MAXD];
__device__ float g_y[NTOT * 2];
__device__ float g_xbuf[2][NTOT * 2];
__device__ unsigned g_count;
__device__ volatile unsigned g_gen;

// ---------------- stage 0: concat + bf16 copy --------------------------------
__global__ void k_concat(const float* __restrict__ lab, const float* __restrict__ unlab) {
    size_t nl  = (size_t)NSUP * DIM;
    size_t tot = (size_t)NTOT * DIM;
    for (size_t idx = blockIdx.x * (size_t)blockDim.x + threadIdx.x; idx < tot;
         idx += gridDim.x * (size_t)blockDim.x) {
        float v = (idx < nl) ? lab[idx] : unlab[idx - nl];
        g_X[idx] = v;
        g_Xh[idx] = __float2bfloat16_rn(v);
    }
}

// ---------------- stage 1: row squared norms ---------------------------------
__global__ void k_sq() {
    int i = blockIdx.x, tid = threadIdx.x;
    __shared__ float red[256];
    const float* r = g_X + (size_t)i * DIM;
    float s = 0.f;
    for (int k = tid; k < DIM; k += 256) { float v = r[k]; s += v * v; }
    red[tid] = s; __syncthreads();
    for (int st = 128; st > 0; st >>= 1) {
        if (tid < st) red[tid] += red[tid + st];
        __syncthreads();
    }
    if (tid == 0) g_sq[i] = red[0];
}

// ---------------- stage 2: single-term bf16 wmma GEMM, K=32 pipeline ---------
__global__ void __launch_bounds__(256, 2) k_gemm() {
    int bi = blockIdx.y, bj = blockIdx.x;
    if (bj < bi) return;
    __shared__ __align__(16) __nv_bfloat16 S[2][2][128 * GSKW];   // 40 KB

    int tid = threadIdx.x;
    int wid = tid >> 5;
    int rA = bi * 128, rB = bj * 128;
    int mbase = (wid >> 2) * 64, nbase = (wid & 3) * 32;

    wmma::fragment<wmma::accumulator, 16, 16, 16, float> acc[4][2];
    #pragma unroll
    for (int u = 0; u < 4; u++)
        #pragma unroll
        for (int v = 0; v < 2; v++) wmma::fill_fragment(acc[u][v], 0.0f);

    int r0 = tid >> 2,          p0 = (tid & 3) * 8;
    int r1 = (tid + 256) >> 2,  p1 = ((tid + 256) & 3) * 8;

    const int NKT = DIM / 32;                  // 32 stages

    __pipeline_memcpy_async(&S[0][0][r0 * GSKW + p0], &g_Xh[(size_t)(rA + r0) * DIM + p0], 16);
    __pipeline_memcpy_async(&S[0][0][r1 * GSKW + p1], &g_Xh[(size_t)(rA + r1) * DIM + p1], 16);
    __pipeline_memcpy_async(&S[0][1][r0 * GSKW + p0], &g_Xh[(size_t)(rB + r0) * DIM + p0], 16);
    __pipeline_memcpy_async(&S[0][1][r1 * GSKW + p1], &g_Xh[(size_t)(rB + r1) * DIM + p1], 16);
    __pipeline_commit();

    for (int kt = 0; kt < NKT; kt++) {
        __pipeline_wait_prior(0);
        __syncthreads();
        if (kt + 1 < NKT) {
            int st = (kt + 1) & 1;
            size_t ko = (size_t)(kt + 1) * 32;
            __pipeline_memcpy_async(&S[st][0][r0 * GSKW + p0], &g_Xh[(size_t)(rA + r0) * DIM + ko + p0], 16);
            __pipeline_memcpy_async(&S[st][0][r1 * GSKW + p1], &g_Xh[(size_t)(rA + r1) * DIM + ko + p1], 16);
            __pipeline_memcpy_async(&S[st][1][r0 * GSKW + p0], &g_Xh[(size_t)(rB + r0) * DIM + ko + p0], 16);
            __pipeline_memcpy_async(&S[st][1][r1 * GSKW + p1], &g_Xh[(size_t)(rB + r1) * DIM + ko + p1], 16);
            __pipeline_commit();
        }

        int st = kt & 1;
        #pragma unroll
        for (int kk = 0; kk < 32; kk += 16) {
            wmma::fragment<wmma::matrix_b, 16, 16, 16, __nv_bfloat16, wmma::col_major> bh[2];
            #pragma unroll
            for (int v = 0; v < 2; v++)
                wmma::load_matrix_sync(bh[v], &S[st][1][(nbase + v * 16) * GSKW + kk], GSKW);
            #pragma unroll
            for (int u = 0; u < 4; u++) {
                wmma::fragment<wmma::matrix_a, 16, 16, 16, __nv_bfloat16, wmma::row_major> ah;
                wmma::load_matrix_sync(ah, &S[st][0][(mbase + u * 16) * GSKW + kk], GSKW);
                #pragma unroll
                for (int v = 0; v < 2; v++)
                    wmma::mma_sync(acc[u][v], ah, bh[v], acc[u][v]);
            }
        }
    }

    #pragma unroll
    for (int u = 0; u < 4; u++)
        #pragma unroll
        for (int v = 0; v < 2; v++) {
            int gi = rA + mbase + u * 16;
            int gj = rB + nbase + v * 16;
            wmma::store_matrix_sync(&g_G[(size_t)gi * NTOT + gj], acc[u][v],
                                    NTOT, wmma::mem_row_major);
            if (bi != bj)
                wmma::store_matrix_sync(&g_G[(size_t)gj * NTOT + gi], acc[u][v],
                                        NTOT, wmma::mem_col_major);
        }
}

// ---------------- stage 3: threshold-collect candidate sets ------------------
__global__ void k_topk() {
    int i = blockIdx.x, tid = threadIdx.x;
    int lane = tid & 31, warp = tid >> 5;
    __shared__ float swv[32];
    __shared__ float s_T;
    __shared__ int   s_cnt;
    __shared__ int   s_list[CAP];

    float sqi = g_sq[i];
    const float4* Grow = (const float4*)(g_G + (size_t)i * NTOT);

    float4 gg[4];
    #pragma unroll
    for (int t = 0; t < 4; t++) gg[t] = Grow[tid + t * 256];

    float bd[4]  = { INFINITY, INFINITY, INFINITY, INFINITY };
    int   bix[4] = { 0x7fffffff, 0x7fffffff, 0x7fffffff, 0x7fffffff };

    #pragma unroll
    for (int t = 0; t < 4; t++) {
        int j4 = tid + t * 256;
        float gv[4] = { gg[t].x, gg[t].y, gg[t].z, gg[t].w };
        #pragma unroll
        for (int e = 0; e < 4; e++) {
            int j = j4 * 4 + e;
            if (j == i) continue;
            float dv = sqi + g_sq[j] - 2.0f * gv[e];
            if (dv < bd[3]) {
                bd[3] = dv; bix[3] = j;
                #pragma unroll
                for (int q = 3; q > 0; q--) {
                    if (bd[q] < bd[q - 1]) {
                        float td = bd[q]; bd[q] = bd[q - 1]; bd[q - 1] = td;
                        int ti = bix[q]; bix[q] = bix[q - 1]; bix[q - 1] = ti;
                    } else break;
                }
            }
        }
    }

    unsigned used = 0;
    for (int r = 0; r < 4; r++) {
        float cv = INFINITY; int ci = 0x7fffffff; int cq = -1;
        #pragma unroll
        for (int q = 0; q < 4; q++) {
            if (!((used >> q) & 1u)) {
                if (bd[q] < cv || (bd[q] == cv && bix[q] < ci)) {
                    cv = bd[q]; ci = bix[q]; cq = q;
                }
            }
        }
        float mv = cv; int mi = ci;
        #pragma unroll
        for (int o = 16; o > 0; o >>= 1) {
            float ov = __shfl_xor_sync(0xffffffffu, cv, o);
            int   oi = __shfl_xor_sync(0xffffffffu, ci, o);
            if (ov < cv || (ov == cv && oi < ci)) { cv = ov; ci = oi; }
        }
        if (cq >= 0 && mi == ci && mv == cv) used |= (1u << cq);
        if (lane == 0) swv[warp * 4 + r] = cv;
    }
    __syncthreads();

    if (tid == 0) {
        int head[8] = {0, 0, 0, 0, 0, 0, 0, 0};
        float v4 = INFINITY;
        for (int r = 0; r < 4; r++) {
            float best = INFINITY; int bw = 0;
            for (int w = 0; w < 8; w++) {
                if (head[w] < 4) {
                    float v = swv[w * 4 + head[w]];
                    if (v < best) { best = v; bw = w; }
                }
            }
            head[bw]++;
            v4 = best;
        }
        s_T = v4 + 1.25f;                       // wide margin vs bf16 screen noise
        s_cnt = 0;
    }
    __syncthreads();
    float T = s_T;

    #pragma unroll
    for (int t = 0; t < 4; t++) {
        int j4 = tid + t * 256;
        float gv[4] = { gg[t].x, gg[t].y, gg[t].z, gg[t].w };
        #pragma unroll
        for (int e = 0; e < 4; e++) {
            int j = j4 * 4 + e;
            if (j == i) continue;
            float dv = sqi + g_sq[j] - 2.0f * gv[e];
            if (dv <= T) {
                int s = atomicAdd(&s_cnt, 1);
                if (s < CAP) s_list[s] = j;
            }
        }
    }
    __syncthreads();
    int cnt = s_cnt < CAP ? s_cnt : CAP;
    if (tid == 0) g_candn[i] = cnt;
    for (int s = tid; s < cnt; s += 256) g_cand[(size_t)i * CAP + s] = s_list[s];
}

// ---------------- stage 3b: fp64 refine -> exact top-4 + exact distances -----
__global__ void __launch_bounds__(256) k_refine() {
    int i = blockIdx.x;
    int warp = threadIdx.x >> 5, lane = threadIdx.x & 31;
    int M = g_candn[i];
    __shared__ double dd[CAP];
    __shared__ int    cid[CAP];

    const float* xi = g_X + (size_t)i * DIM;
    for (int c = warp; c < M; c += 8) {
        int j = g_cand[(size_t)i * CAP + c];
        const float* xj = g_X + (size_t)j * DIM;
        double s = 0.0;
        for (int k = lane; k < DIM; k += 32) {
            double d = (double)xi[k] - (double)xj[k];
            s += d * d;
        }
        #pragma unroll
        for (int o = 16; o > 0; o >>= 1) s += __shfl_down_sync(0xffffffffu, s, o);
        if (lane == 0) { dd[c] = s; cid[c] = j; }
    }
    __syncthreads();
    if (threadIdx.x == 0) {
        for (int r = 0; r < 4; r++) {
            int best = -1;
            for (int c = 0; c < M; c++) {
                if (best < 0 || dd[c] < dd[best] ||
                    (dd[c] == dd[best] && cid[c] < cid[best])) best = c;
            }
            g_top4[i * 4 + r]  = cid[best];
            g_adist[i * 4 + r] = (float)(dd[best] * (1.0 / 1024.0));
            dd[best] = 1e300;
        }
    }
}

// ---------------- stage 4: symmetric adjacency + edge distances --------------
__global__ void k_adj() {
    int i = blockIdx.x, tid = threadIdx.x;          // 128 threads
    __shared__ int   myt[4];
    __shared__ float mytd[4];
    __shared__ int counts[128];
    __shared__ int offs[128];
    if (tid < 4) { myt[tid] = g_top4[i * 4 + tid]; mytd[tid] = g_adist[i * 4 + tid]; }
    __syncthreads();
    int t0 = myt[0], t1 = myt[1], t2 = myt[2], t3 = myt[3];

    int   local[32];
    float locd[32];
    int cnt = 0;
    int j0 = tid * 32;
    for (int q = 0; q < 32; q++) {
        int j = j0 + q;
        int4 tj = *(const int4*)&g_top4[j * 4];
        int r = (tj.x == i) ? 0 : (tj.y == i) ? 1 : (tj.z == i) ? 2 : (tj.w == i) ? 3 : -1;
        if (r >= 0 && j != t0 && j != t1 && j != t2 && j != t3) {
            local[cnt] = j;
            locd[cnt] = g_adist[j * 4 + r];     // dist(j,i) == dist(i,j), exact
            cnt++;
        }
    }
    counts[tid] = cnt;
    __syncthreads();
    if (tid == 0) {
        int s = 0;
        for (int k = 0; k < 128; k++) { offs[k] = s; s += counts[k]; }
        int dg = 4 + s;
        g_deg[i] = dg > MAXD ? MAXD : dg;
    }
    __syncthreads();
    int base = 4 + offs[tid];
    for (int q = 0; q < cnt; q++) {
        if (base + q < MAXD) {
            g_adj [(size_t)i * MAXD + base + q] = local[q];
            g_adjd[(size_t)i * MAXD + base + q] = locd[q];
        }
    }
    if (tid < 4) {
        g_adj [(size_t)i * MAXD + tid] = myt[tid];
        g_adjd[(size_t)i * MAXD + tid] = mytd[tid];
    }
}

// ---------------- stage 5: edge weights (lookup) + D + y ---------------------
__global__ void k_weights(const int* __restrict__ tgt) {
    int i = blockIdx.x * blockDim.x + threadIdx.x;
    if (i >= NTOT) return;
    int dg = g_deg[i];
    float s = 0.f;
    for (int l = 0; l < dg; l++) {
        float w = expf(-0.5f * g_adjd[(size_t)i * MAXD + l]);
        g_Wv[(size_t)i * MAXD + l] = w;
        s += w;
    }
    g_D[i] = s;
    float y0 = 0.f, y1 = 0.f;
    if (i < NSUP) {
        int t = tgt[i];
        y0 = (t == 0) ? 1.f : 0.f;
        y1 = (t == 1) ? 1.f : 0.f;
    }
    g_y[2 * i] = y0;
    g_y[2 * i + 1] = y1;
}

// ---------------- stage 6: packed edges, alpha * (d_i * W * d_j) -------------
__global__ void k_scale() {
    int i = blockIdx.x * blockDim.x + threadIdx.x;
    if (i >= NTOT) return;
    const float EPSF = 2.220446049250313e-16f;
    int dg = g_deg[i];
    float ri = sqrtf(1.0f / (g_D[i] + EPSF));
    for (int l = 0; l < dg; l++) {
        int j = g_adj[(size_t)i * MAXD + l];
        float rj = sqrtf(1.0f / (g_D[j] + EPSF));
        float sv = 0.99f * ((ri * g_Wv[(size_t)i * MAXD + l]) * rj);
        g_edge[(size_t)i * MAXD + l] = make_int2(j, __float_as_int(sv));
    }
}

// ---------------- grid barrier (writer-only fence) ----------------------------
__device__ __forceinline__ void gridbar(bool writer) {
    if (writer) __threadfence();
    __syncthreads();
    if (threadIdx.x == 0) {
        unsigned my = g_gen;
        if (atomicAdd(&g_count, 1) == SBLK - 1) {
            g_count = 0;
            __threadfence();
            g_gen = my + 1;
        } else {
            while (g_gen == my) { __nanosleep(32); }
        }
        __threadfence();
    }
    __syncthreads();
}

// ---------------- stage 8: Chebyshev solve, 32 CTAs, 8 lanes per row ---------
__global__ void __launch_bounds__(1024, 1) k_solve(float* __restrict__ out) {
    unsigned gtid = blockIdx.x * 1024u + threadIdx.x;
    int row = gtid >> 3;
    int q8  = gtid & 7;
    bool writer = (q8 == 0);

    const float theta = 1.0f, delta = 0.99f;
    const float sigma = theta / delta;
    float rho_prev = delta / theta;

    float b0 = g_y[2 * row], b1 = g_y[2 * row + 1];
    float d0 = b0, d1 = b1;
    float x0 = b0, x1 = b1;
    int dg = g_deg[row];
    const int2* ep = g_edge + (size_t)row * MAXD;

    if (writer)
        __stcg((float2*)&g_xbuf[0][2 * row], make_float2(x0, x1));
    gridbar(writer);
    int p = 0;

    for (int it = 1; it < NITER; ++it) {
        float s0 = 0.f, s1 = 0.f;
        for (int l = q8; l < dg; l += 8) {
            int2 e = __ldg(&ep[l]);
            float w = __int_as_float(e.y);
            float2 xj = __ldcg((const float2*)&g_xbuf[p][2 * e.x]);
            s0 += w * xj.x;
            s1 += w * xj.y;
        }
        s0 += __shfl_down_sync(0xffffffffu, s0, 4, 8);
        s1 += __shfl_down_sync(0xffffffffu, s1, 4, 8);
        s0 += __shfl_down_sync(0xffffffffu, s0, 2, 8);
        s1 += __shfl_down_sync(0xffffffffu, s1, 2, 8);
        s0 += __shfl_down_sync(0xffffffffu, s0, 1, 8);
        s1 += __shfl_down_sync(0xffffffffu, s1, 1, 8);

        float rho = 1.0f / (2.0f * sigma - rho_prev);
        float c1 = rho * rho_prev, c2 = 2.0f * rho / delta;
        if (writer) {
            float rr0 = b0 - x0 + s0;
            float rr1 = b1 - x1 + s1;
            d0 = c1 * d0 + c2 * rr0;
            d1 = c1 * d1 + c2 * rr1;
            x0 += d0;
            x1 += d1;
            if (it != NITER - 1)
                __stcg((float2*)&g_xbuf[1 - p][2 * row], make_float2(x0, x1));
        }
        rho_prev = rho;
        if (it != NITER - 1) {
            gridbar(writer);
            p ^= 1;
        }
    }

    if (writer && row >= NSUP) {
        out[2 * (row - NSUP)]     = x0;
        out[2 * (row - NSUP) + 1] = x1;
    }
}

// ---------------- launch ------------------------------------------------------
extern "C" void kernel_launch(void* const* d_in, const int* in_sizes, int n_in,
                              void* d_out, int out_size) {
    const float* lab   = (const float*)d_in[0];
    const int*   tgt   = (const int*)d_in[1];
    const float* unlab = (const float*)d_in[2];
    float* out = (float*)d_out;

    k_concat<<<2048, 256>>>(lab, unlab);
    k_sq<<<NTOT, 256>>>();
    dim3 gg(32, 32);
    k_gemm<<<gg, 256>>>();
    k_topk<<<NTOT, 256>>>();
    k_refine<<<NTOT, 256>>>();
    k_adj<<<NTOT, 128>>>();
    k_weights<<<(NTOT + 255) / 256, 256>>>(tgt);
    k_scale<<<(NTOT + 255) / 256, 256>>>();
    k_solve<<<SBLK, 1024>>>(out);
}

// round 14
// speedup vs baseline: 1.7236x; 1.1125x over previous
#include <cuda_runtime.h>
#include <cuda_bf16.h>
#include <cuda_pipeline.h>
#include <mma.h>
#include <math.h>
#include <stdint.h>

using namespace nvcuda;

#define NTOT 4096
#define NSUP 1024
#define DIM  1024
#define MAXD 1024
#define CAP  192
#define NITER 72
#define SBLK 32
#define GSKW 24                                    // smem stride (bf16), 48B
#define GST  4                                     // pipeline stages (K=16 each)

// ---------------- device scratch (allocation-free: __device__ globals) ------
__device__ float g_X [(size_t)NTOT * DIM];          // 16 MB fp32 inputs
__device__ __nv_bfloat16 g_Xh[(size_t)NTOT * DIM];  // 8 MB bf16
__device__ float g_G [(size_t)NTOT * NTOT];         // 64 MB Gram (bf16-accurate)
__device__ float g_sq[NTOT];
__device__ int   g_cand[(size_t)NTOT * CAP];        // 3 MB candidate sets
__device__ int   g_candn[NTOT];
__device__ __align__(16) int g_top4[NTOT * 4];
__device__ float g_adist[NTOT * 4];                 // exact normalized dist of top4
__device__ int   g_adj[(size_t)NTOT * MAXD];
__device__ float g_adjd[(size_t)NTOT * MAXD];       // per-edge exact dist
__device__ int   g_deg[NTOT];
__device__ float g_Wv[(size_t)NTOT * MAXD];
__device__ float g_D[NTOT];
__device__ int2  g_edge[(size_t)NTOT * MAXD];
__device__ float g_y[NTOT * 2];
__device__ float g_xbuf[2][NTOT * 2];
__device__ unsigned g_count;
__device__ volatile unsigned g_gen;

// ---------------- stage 0: concat + bf16 copy --------------------------------
__global__ void k_concat(const float* __restrict__ lab, const float* __restrict__ unlab) {
    size_t nl  = (size_t)NSUP * DIM;
    size_t tot = (size_t)NTOT * DIM;
    for (size_t idx = blockIdx.x * (size_t)blockDim.x + threadIdx.x; idx < tot;
         idx += gridDim.x * (size_t)blockDim.x) {
        float v = (idx < nl) ? lab[idx] : unlab[idx - nl];
        g_X[idx] = v;
        g_Xh[idx] = __float2bfloat16_rn(v);
    }
}

// ---------------- stage 1: row squared norms ---------------------------------
__global__ void k_sq() {
    int i = blockIdx.x, tid = threadIdx.x;
    __shared__ float red[256];
    const float* r = g_X + (size_t)i * DIM;
    float s = 0.f;
    for (int k = tid; k < DIM; k += 256) { float v = r[k]; s += v * v; }
    red[tid] = s; __syncthreads();
    for (int st = 128; st > 0; st >>= 1) {
        if (tid < st) red[tid] += red[tid + st];
        __syncthreads();
    }
    if (tid == 0) g_sq[i] = red[0];
}

// ---------------- stage 2: bf16 wmma GEMM, 4-stage cp.async ring -------------
__global__ void __launch_bounds__(256, 2) k_gemm() {
    int bi = blockIdx.y, bj = blockIdx.x;
    if (bj < bi) return;
    __shared__ __align__(16) __nv_bfloat16 S[GST][2][128 * GSKW];   // 48 KB

    int tid = threadIdx.x;
    int wid = tid >> 5;
    int rA = bi * 128, rB = bj * 128;
    int mbase = (wid >> 2) * 64, nbase = (wid & 3) * 32;

    wmma::fragment<wmma::accumulator, 16, 16, 16, float> acc[4][2];
    #pragma unroll
    for (int u = 0; u < 4; u++)
        #pragma unroll
        for (int v = 0; v < 2; v++) wmma::fill_fragment(acc[u][v], 0.0f);

    int lr = tid >> 1, lp = (tid & 1) * 8;     // 128 rows x 2 chunks of 16B
    size_t srcA = (size_t)(rA + lr) * DIM + lp;
    size_t srcB = (size_t)(rB + lr) * DIM + lp;
    unsigned dst = lr * GSKW + lp;

    const int NKT = DIM / 16;                  // 64 stages of K=16

    // prologue: stages 0..2
    #pragma unroll
    for (int s = 0; s < GST - 1; s++) {
        __pipeline_memcpy_async(&S[s][0][dst], &g_Xh[srcA + (size_t)s * 16], 16);
        __pipeline_memcpy_async(&S[s][1][dst], &g_Xh[srcB + (size_t)s * 16], 16);
        __pipeline_commit();
    }

    for (int kt = 0; kt < NKT; kt++) {
        __pipeline_wait_prior(GST - 2);        // stage kt resident
        __syncthreads();                       // also retires reads of buf being refilled
        if (kt + GST - 1 < NKT) {
            int sb = (kt + GST - 1) & (GST - 1);
            size_t ko = (size_t)(kt + GST - 1) * 16;
            __pipeline_memcpy_async(&S[sb][0][dst], &g_Xh[srcA + ko], 16);
            __pipeline_memcpy_async(&S[sb][1][dst], &g_Xh[srcB + ko], 16);
        }
        __pipeline_commit();                   // real or empty: keeps group count exact

        int st = kt & (GST - 1);
        wmma::fragment<wmma::matrix_b, 16, 16, 16, __nv_bfloat16, wmma::col_major> bh[2];
        #pragma unroll
        for (int v = 0; v < 2; v++)
            wmma::load_matrix_sync(bh[v], &S[st][1][(nbase + v * 16) * GSKW], GSKW);
        #pragma unroll
        for (int u = 0; u < 4; u++) {
            wmma::fragment<wmma::matrix_a, 16, 16, 16, __nv_bfloat16, wmma::row_major> ah;
            wmma::load_matrix_sync(ah, &S[st][0][(mbase + u * 16) * GSKW], GSKW);
            #pragma unroll
            for (int v = 0; v < 2; v++)
                wmma::mma_sync(acc[u][v], ah, bh[v], acc[u][v]);
        }
    }

    #pragma unroll
    for (int u = 0; u < 4; u++)
        #pragma unroll
        for (int v = 0; v < 2; v++) {
            int gi = rA + mbase + u * 16;
            int gj = rB + nbase + v * 16;
            wmma::store_matrix_sync(&g_G[(size_t)gi * NTOT + gj], acc[u][v],
                                    NTOT, wmma::mem_row_major);
            if (bi != bj)
                wmma::store_matrix_sync(&g_G[(size_t)gj * NTOT + gi], acc[u][v],
                                        NTOT, wmma::mem_col_major);
        }
}

// ---------------- stage 3: threshold-collect candidate sets ------------------
__global__ void k_topk() {
    int i = blockIdx.x, tid = threadIdx.x;
    int lane = tid & 31, warp = tid >> 5;
    __shared__ float swv[32];
    __shared__ float s_T;
    __shared__ int   s_cnt;
    __shared__ int   s_list[CAP];

    float sqi = g_sq[i];
    const float4* Grow = (const float4*)(g_G + (size_t)i * NTOT);

    float4 gg[4];
    #pragma unroll
    for (int t = 0; t < 4; t++) gg[t] = Grow[tid + t * 256];

    float bd[4]  = { INFINITY, INFINITY, INFINITY, INFINITY };
    int   bix[4] = { 0x7fffffff, 0x7fffffff, 0x7fffffff, 0x7fffffff };

    #pragma unroll
    for (int t = 0; t < 4; t++) {
        int j4 = tid + t * 256;
        float gv[4] = { gg[t].x, gg[t].y, gg[t].z, gg[t].w };
        #pragma unroll
        for (int e = 0; e < 4; e++) {
            int j = j4 * 4 + e;
            if (j == i) continue;
            float dv = sqi + g_sq[j] - 2.0f * gv[e];
            if (dv < bd[3]) {
                bd[3] = dv; bix[3] = j;
                #pragma unroll
                for (int q = 3; q > 0; q--) {
                    if (bd[q] < bd[q - 1]) {
                        float td = bd[q]; bd[q] = bd[q - 1]; bd[q - 1] = td;
                        int ti = bix[q]; bix[q] = bix[q - 1]; bix[q - 1] = ti;
                    } else break;
                }
            }
        }
    }

    unsigned used = 0;
    for (int r = 0; r < 4; r++) {
        float cv = INFINITY; int ci = 0x7fffffff; int cq = -1;
        #pragma unroll
        for (int q = 0; q < 4; q++) {
            if (!((used >> q) & 1u)) {
                if (bd[q] < cv || (bd[q] == cv && bix[q] < ci)) {
                    cv = bd[q]; ci = bix[q]; cq = q;
                }
            }
        }
        float mv = cv; int mi = ci;
        #pragma unroll
        for (int o = 16; o > 0; o >>= 1) {
            float ov = __shfl_xor_sync(0xffffffffu, cv, o);
            int   oi = __shfl_xor_sync(0xffffffffu, ci, o);
            if (ov < cv || (ov == cv && oi < ci)) { cv = ov; ci = oi; }
        }
        if (cq >= 0 && mi == ci && mv == cv) used |= (1u << cq);
        if (lane == 0) swv[warp * 4 + r] = cv;
    }
    __syncthreads();

    if (tid == 0) {
        int head[8] = {0, 0, 0, 0, 0, 0, 0, 0};
        float v4 = INFINITY;
        for (int r = 0; r < 4; r++) {
            float best = INFINITY; int bw = 0;
            for (int w = 0; w < 8; w++) {
                if (head[w] < 4) {
                    float v = swv[w * 4 + head[w]];
                    if (v < best) { best = v; bw = w; }
                }
            }
            head[bw]++;
            v4 = best;
        }
        s_T = v4 + 1.25f;                       // wide margin vs bf16 screen noise
        s_cnt = 0;
    }
    __syncthreads();
    float T = s_T;

    #pragma unroll
    for (int t = 0; t < 4; t++) {
        int j4 = tid + t * 256;
        float gv[4] = { gg[t].x, gg[t].y, gg[t].z, gg[t].w };
        #pragma unroll
        for (int e = 0; e < 4; e++) {
            int j = j4 * 4 + e;
            if (j == i) continue;
            float dv = sqi + g_sq[j] - 2.0f * gv[e];
            if (dv <= T) {
                int s = atomicAdd(&s_cnt, 1);
                if (s < CAP) s_list[s] = j;
            }
        }
    }
    __syncthreads();
    int cnt = s_cnt < CAP ? s_cnt : CAP;
    if (tid == 0) g_candn[i] = cnt;
    for (int s = tid; s < cnt; s += 256) g_cand[(size_t)i * CAP + s] = s_list[s];
}

// ---------------- stage 3b: fp64 refine -> exact top-4 + exact distances -----
__global__ void __launch_bounds__(256) k_refine() {
    int i = blockIdx.x;
    int warp = threadIdx.x >> 5, lane = threadIdx.x & 31;
    int M = g_candn[i];
    __shared__ double dd[CAP];
    __shared__ int    cid[CAP];

    const float* xi = g_X + (size_t)i * DIM;
    for (int c = warp; c < M; c += 8) {
        int j = g_cand[(size_t)i * CAP + c];
        const float* xj = g_X + (size_t)j * DIM;
        double s = 0.0;
        for (int k = lane; k < DIM; k += 32) {
            double d = (double)xi[k] - (double)xj[k];
            s += d * d;
        }
        #pragma unroll
        for (int o = 16; o > 0; o >>= 1) s += __shfl_down_sync(0xffffffffu, s, o);
        if (lane == 0) { dd[c] = s; cid[c] = j; }
    }
    __syncthreads();
    if (threadIdx.x == 0) {
        for (int r = 0; r < 4; r++) {
            int best = -1;
            for (int c = 0; c < M; c++) {
                if (best < 0 || dd[c] < dd[best] ||
                    (dd[c] == dd[best] && cid[c] < cid[best])) best = c;
            }
            g_top4[i * 4 + r]  = cid[best];
            g_adist[i * 4 + r] = (float)(dd[best] * (1.0 / 1024.0));
            dd[best] = 1e300;
        }
    }
}

// ---------------- stage 4: symmetric adjacency + edge distances --------------
__global__ void k_adj() {
    int i = blockIdx.x, tid = threadIdx.x;          // 128 threads
    __shared__ int   myt[4];
    __shared__ float mytd[4];
    __shared__ int counts[128];
    __shared__ int offs[128];
    if (tid < 4) { myt[tid] = g_top4[i * 4 + tid]; mytd[tid] = g_adist[i * 4 + tid]; }
    __syncthreads();
    int t0 = myt[0], t1 = myt[1], t2 = myt[2], t3 = myt[3];

    int   local[32];
    float locd[32];
    int cnt = 0;
    int j0 = tid * 32;
    for (int q = 0; q < 32; q++) {
        int j = j0 + q;
        int4 tj = *(const int4*)&g_top4[j * 4];
        int r = (tj.x == i) ? 0 : (tj.y == i) ? 1 : (tj.z == i) ? 2 : (tj.w == i) ? 3 : -1;
        if (r >= 0 && j != t0 && j != t1 && j != t2 && j != t3) {
            local[cnt] = j;
            locd[cnt] = g_adist[j * 4 + r];     // dist(j,i) == dist(i,j), exact
            cnt++;
        }
    }
    counts[tid] = cnt;
    __syncthreads();
    if (tid == 0) {
        int s = 0;
        for (int k = 0; k < 128; k++) { offs[k] = s; s += counts[k]; }
        int dg = 4 + s;
        g_deg[i] = dg > MAXD ? MAXD : dg;
    }
    __syncthreads();
    int base = 4 + offs[tid];
    for (int q = 0; q < cnt; q++) {
        if (base + q < MAXD) {
            g_adj [(size_t)i * MAXD + base + q] = local[q];
            g_adjd[(size_t)i * MAXD + base + q] = locd[q];
        }
    }
    if (tid < 4) {
        g_adj [(size_t)i * MAXD + tid] = myt[tid];
        g_adjd[(size_t)i * MAXD + tid] = mytd[tid];
    }
}

// ---------------- stage 5: edge weights (lookup) + D + y ---------------------
__global__ void k_weights(const int* __restrict__ tgt) {
    int i = blockIdx.x * blockDim.x + threadIdx.x;
    if (i >= NTOT) return;
    int dg = g_deg[i];
    float s = 0.f;
    for (int l = 0; l < dg; l++) {
        float w = expf(-0.5f * g_adjd[(size_t)i * MAXD + l]);
        g_Wv[(size_t)i * MAXD + l] = w;
        s += w;
    }
    g_D[i] = s;
    float y0 = 0.f, y1 = 0.f;
    if (i < NSUP) {
        int t = tgt[i];
        y0 = (t == 0) ? 1.f : 0.f;
        y1 = (t == 1) ? 1.f : 0.f;
    }
    g_y[2 * i] = y0;
    g_y[2 * i + 1] = y1;
}

// ---------------- stage 6: packed edges, alpha * (d_i * W * d_j) -------------
__global__ void k_scale() {
    int i = blockIdx.x * blockDim.x + threadIdx.x;
    if (i >= NTOT) return;
    const float EPSF = 2.220446049250313e-16f;
    int dg = g_deg[i];
    float ri = sqrtf(1.0f / (g_D[i] + EPSF));
    for (int l = 0; l < dg; l++) {
        int j = g_adj[(size_t)i * MAXD + l];
        float rj = sqrtf(1.0f / (g_D[j] + EPSF));
        float sv = 0.99f * ((ri * g_Wv[(size_t)i * MAXD + l]) * rj);
        g_edge[(size_t)i * MAXD + l] = make_int2(j, __float_as_int(sv));
    }
}

// ---------------- grid barrier (writer-only fence) ----------------------------
__device__ __forceinline__ void gridbar(bool writer) {
    if (writer) __threadfence();
    __syncthreads();
    if (threadIdx.x == 0) {
        unsigned my = g_gen;
        if (atomicAdd(&g_count, 1) == SBLK - 1) {
            g_count = 0;
            __threadfence();
            g_gen = my + 1;
        } else {
            while (g_gen == my) { __nanosleep(32); }
        }
        __threadfence();
    }
    __syncthreads();
}

// ---------------- stage 8: Chebyshev solve, 32 CTAs, 8 lanes per row ---------
__global__ void __launch_bounds__(1024, 1) k_solve(float* __restrict__ out) {
    unsigned gtid = blockIdx.x * 1024u + threadIdx.x;
    int row = gtid >> 3;
    int q8  = gtid & 7;
    bool writer = (q8 == 0);

    const float theta = 1.0f, delta = 0.99f;
    const float sigma = theta / delta;
    float rho_prev = delta / theta;

    float b0 = g_y[2 * row], b1 = g_y[2 * row + 1];
    float d0 = b0, d1 = b1;
    float x0 = b0, x1 = b1;
    int dg = g_deg[row];
    const int2* ep = g_edge + (size_t)row * MAXD;

    if (writer)
        __stcg((float2*)&g_xbuf[0][2 * row], make_float2(x0, x1));
    gridbar(writer);
    int p = 0;

    for (int it = 1; it < NITER; ++it) {
        float s0 = 0.f, s1 = 0.f;
        for (int l = q8; l < dg; l += 8) {
            int2 e = __ldg(&ep[l]);
            float w = __int_as_float(e.y);
            float2 xj = __ldcg((const float2*)&g_xbuf[p][2 * e.x]);
            s0 += w * xj.x;
            s1 += w * xj.y;
        }
        s0 += __shfl_down_sync(0xffffffffu, s0, 4, 8);
        s1 += __shfl_down_sync(0xffffffffu, s1, 4, 8);
        s0 += __shfl_down_sync(0xffffffffu, s0, 2, 8);
        s1 += __shfl_down_sync(0xffffffffu, s1, 2, 8);
        s0 += __shfl_down_sync(0xffffffffu, s0, 1, 8);
        s1 += __shfl_down_sync(0xffffffffu, s1, 1, 8);

        float rho = 1.0f / (2.0f * sigma - rho_prev);
        float c1 = rho * rho_prev, c2 = 2.0f * rho / delta;
        if (writer) {
            float rr0 = b0 - x0 + s0;
            float rr1 = b1 - x1 + s1;
            d0 = c1 * d0 + c2 * rr0;
            d1 = c1 * d1 + c2 * rr1;
            x0 += d0;
            x1 += d1;
            if (it != NITER - 1)
                __stcg((float2*)&g_xbuf[1 - p][2 * row], make_float2(x0, x1));
        }
        rho_prev = rho;
        if (it != NITER - 1) {
            gridbar(writer);
            p ^= 1;
        }
    }

    if (writer && row >= NSUP) {
        out[2 * (row - NSUP)]     = x0;
        out[2 * (row - NSUP) + 1] = x1;
    }
}

// ---------------- launch ------------------------------------------------------
extern "C" void kernel_launch(void* const* d_in, const int* in_sizes, int n_in,
                              void* d_out, int out_size) {
    const float* lab   = (const float*)d_in[0];
    const int*   tgt   = (const int*)d_in[1];
    const float* unlab = (const float*)d_in[2];
    float* out = (float*)d_out;

    k_concat<<<2048, 256>>>(lab, unlab);
    k_sq<<<NTOT, 256>>>();
    dim3 gg(32, 32);
    k_gemm<<<gg, 256>>>();
    k_topk<<<NTOT, 256>>>();
    k_refine<<<NTOT, 256>>>();
    k_adj<<<NTOT, 128>>>();
    k_weights<<<(NTOT + 255) / 256, 256>>>(tgt);
    k_scale<<<(NTOT + 255) / 256, 256>>>();
    k_solve<<<SBLK, 1024>>>(out);
}

// round 16
// speedup vs baseline: 1.7624x; 1.0225x over previous
#include <cuda_runtime.h>
#include <cuda_bf16.h>
#include <cuda_pipeline.h>
#include <mma.h>
#include <math.h>
#include <stdint.h>

using namespace nvcuda;

#define NTOT 4096
#define NSUP 1024
#define DIM  1024
#define MAXD 1024
#define CAP  192
#define NITER 64
#define SBLK 32
#define GSKW 24                                    // smem stride (bf16), 48B
#define GST  4                                     // pipeline stages (K=16 each)

// ---------------- device scratch (allocation-free: __device__ globals) ------
__device__ float g_X [(size_t)NTOT * DIM];          // 16 MB fp32 inputs
__device__ __nv_bfloat16 g_Xh[(size_t)NTOT * DIM];  // 8 MB bf16
__device__ float g_G [(size_t)NTOT * NTOT];         // 64 MB Gram (bf16-accurate)
__device__ float g_sq[NTOT];
__device__ int   g_cand[(size_t)NTOT * CAP];        // 3 MB candidate sets
__device__ int   g_candn[NTOT];
__device__ __align__(16) int g_top4[NTOT * 4];
__device__ float g_adist[NTOT * 4];                 // exact normalized dist of top4
__device__ int   g_adj[(size_t)NTOT * MAXD];
__device__ float g_adjd[(size_t)NTOT * MAXD];       // per-edge exact dist
__device__ int   g_deg[NTOT];
__device__ float g_Wv[(size_t)NTOT * MAXD];
__device__ float g_D[NTOT];
__device__ int2  g_edge[(size_t)NTOT * MAXD];
__device__ float g_y[NTOT * 2];
__device__ float g_xbuf[2][NTOT * 2];
__device__ unsigned g_count;
__device__ volatile unsigned g_gen;

// ---------------- stage 0: concat + bf16 copy --------------------------------
__global__ void k_concat(const float* __restrict__ lab, const float* __restrict__ unlab) {
    size_t nl  = (size_t)NSUP * DIM;
    size_t tot = (size_t)NTOT * DIM;
    for (size_t idx = blockIdx.x * (size_t)blockDim.x + threadIdx.x; idx < tot;
         idx += gridDim.x * (size_t)blockDim.x) {
        float v = (idx < nl) ? lab[idx] : unlab[idx - nl];
        g_X[idx] = v;
        g_Xh[idx] = __float2bfloat16_rn(v);
    }
}

// ---------------- stage 1: row squared norms ---------------------------------
__global__ void k_sq() {
    int i = blockIdx.x, tid = threadIdx.x;
    __shared__ float red[256];
    const float* r = g_X + (size_t)i * DIM;
    float s = 0.f;
    for (int k = tid; k < DIM; k += 256) { float v = r[k]; s += v * v; }
    red[tid] = s; __syncthreads();
    for (int st = 128; st > 0; st >>= 1) {
        if (tid < st) red[tid] += red[tid + st];
        __syncthreads();
    }
    if (tid == 0) g_sq[i] = red[0];
}

// ---------------- stage 1b: y one-hot (3rd launch -> gemm lands in ncu win) --
__global__ void k_y(const int* __restrict__ tgt) {
    int i = blockIdx.x * blockDim.x + threadIdx.x;
    if (i >= NTOT) return;
    float y0 = 0.f, y1 = 0.f;
    if (i < NSUP) {
        int t = tgt[i];
        y0 = (t == 0) ? 1.f : 0.f;
        y1 = (t == 1) ? 1.f : 0.f;
    }
    g_y[2 * i] = y0;
    g_y[2 * i + 1] = y1;
}

// ---------------- stage 2: bf16 wmma GEMM, 4-stage cp.async ring -------------
__global__ void __launch_bounds__(256, 2) k_gemm() {
    int bi = blockIdx.y, bj = blockIdx.x;
    if (bj < bi) return;
    __shared__ __align__(16) __nv_bfloat16 S[GST][2][128 * GSKW];   // 48 KB

    int tid = threadIdx.x;
    int wid = tid >> 5;
    int rA = bi * 128, rB = bj * 128;
    int mbase = (wid >> 2) * 64, nbase = (wid & 3) * 32;

    wmma::fragment<wmma::accumulator, 16, 16, 16, float> acc[4][2];
    #pragma unroll
    for (int u = 0; u < 4; u++)
        #pragma unroll
        for (int v = 0; v < 2; v++) wmma::fill_fragment(acc[u][v], 0.0f);

    int lr = tid >> 1, lp = (tid & 1) * 8;     // 128 rows x 2 chunks of 16B
    size_t srcA = (size_t)(rA + lr) * DIM + lp;
    size_t srcB = (size_t)(rB + lr) * DIM + lp;
    unsigned dst = lr * GSKW + lp;

    const int NKT = DIM / 16;                  // 64 stages of K=16

    // prologue: stages 0..2
    #pragma unroll
    for (int s = 0; s < GST - 1; s++) {
        __pipeline_memcpy_async(&S[s][0][dst], &g_Xh[srcA + (size_t)s * 16], 16);
        __pipeline_memcpy_async(&S[s][1][dst], &g_Xh[srcB + (size_t)s * 16], 16);
        __pipeline_commit();
    }

    for (int kt = 0; kt < NKT; kt++) {
        __pipeline_wait_prior(GST - 2);        // stage kt resident
        __syncthreads();                       // also retires reads of buf being refilled
        if (kt + GST - 1 < NKT) {
            int sb = (kt + GST - 1) & (GST - 1);
            size_t ko = (size_t)(kt + GST - 1) * 16;
            __pipeline_memcpy_async(&S[sb][0][dst], &g_Xh[srcA + ko], 16);
            __pipeline_memcpy_async(&S[sb][1][dst], &g_Xh[srcB + ko], 16);
        }
        __pipeline_commit();                   // real or empty: keeps group count exact

        int st = kt & (GST - 1);
        wmma::fragment<wmma::matrix_b, 16, 16, 16, __nv_bfloat16, wmma::col_major> bh[2];
        #pragma unroll
        for (int v = 0; v < 2; v++)
            wmma::load_matrix_sync(bh[v], &S[st][1][(nbase + v * 16) * GSKW], GSKW);
        #pragma unroll
        for (int u = 0; u < 4; u++) {
            wmma::fragment<wmma::matrix_a, 16, 16, 16, __nv_bfloat16, wmma::row_major> ah;
            wmma::load_matrix_sync(ah, &S[st][0][(mbase + u * 16) * GSKW], GSKW);
            #pragma unroll
            for (int v = 0; v < 2; v++)
                wmma::mma_sync(acc[u][v], ah, bh[v], acc[u][v]);
        }
    }

    #pragma unroll
    for (int u = 0; u < 4; u++)
        #pragma unroll
        for (int v = 0; v < 2; v++) {
            int gi = rA + mbase + u * 16;
            int gj = rB + nbase + v * 16;
            wmma::store_matrix_sync(&g_G[(size_t)gi * NTOT + gj], acc[u][v],
                                    NTOT, wmma::mem_row_major);
            if (bi != bj)
                wmma::store_matrix_sync(&g_G[(size_t)gj * NTOT + gi], acc[u][v],
                                        NTOT, wmma::mem_col_major);
        }
}

// ---------------- stage 3: threshold-collect candidate sets ------------------
__global__ void k_topk() {
    int i = blockIdx.x, tid = threadIdx.x;
    int lane = tid & 31, warp = tid >> 5;
    __shared__ float swv[32];
    __shared__ float s_T;
    __shared__ int   s_cnt;
    __shared__ int   s_list[CAP];

    float sqi = g_sq[i];
    const float4* Grow = (const float4*)(g_G + (size_t)i * NTOT);

    float4 gg[4];
    #pragma unroll
    for (int t = 0; t < 4; t++) gg[t] = Grow[tid + t * 256];

    float bd[4]  = { INFINITY, INFINITY, INFINITY, INFINITY };
    int   bix[4] = { 0x7fffffff, 0x7fffffff, 0x7fffffff, 0x7fffffff };

    #pragma unroll
    for (int t = 0; t < 4; t++) {
        int j4 = tid + t * 256;
        float gv[4] = { gg[t].x, gg[t].y, gg[t].z, gg[t].w };
        #pragma unroll
        for (int e = 0; e < 4; e++) {
            int j = j4 * 4 + e;
            if (j == i) continue;
            float dv = sqi + g_sq[j] - 2.0f * gv[e];
            if (dv < bd[3]) {
                bd[3] = dv; bix[3] = j;
                #pragma unroll
                for (int q = 3; q > 0; q--) {
                    if (bd[q] < bd[q - 1]) {
                        float td = bd[q]; bd[q] = bd[q - 1]; bd[q - 1] = td;
                        int ti = bix[q]; bix[q] = bix[q - 1]; bix[q - 1] = ti;
                    } else break;
                }
            }
        }
    }

    unsigned used = 0;
    for (int r = 0; r < 4; r++) {
        float cv = INFINITY; int ci = 0x7fffffff; int cq = -1;
        #pragma unroll
        for (int q = 0; q < 4; q++) {
            if (!((used >> q) & 1u)) {
                if (bd[q] < cv || (bd[q] == cv && bix[q] < ci)) {
                    cv = bd[q]; ci = bix[q]; cq = q;
                }
            }
        }
        float mv = cv; int mi = ci;
        #pragma unroll
        for (int o = 16; o > 0; o >>= 1) {
            float ov = __shfl_xor_sync(0xffffffffu, cv, o);
            int   oi = __shfl_xor_sync(0xffffffffu, ci, o);
            if (ov < cv || (ov == cv && oi < ci)) { cv = ov; ci = oi; }
        }
        if (cq >= 0 && mi == ci && mv == cv) used |= (1u << cq);
        if (lane == 0) swv[warp * 4 + r] = cv;
    }
    __syncthreads();

    if (tid == 0) {
        int head[8] = {0, 0, 0, 0, 0, 0, 0, 0};
        float v4 = INFINITY;
        for (int r = 0; r < 4; r++) {
            float best = INFINITY; int bw = 0;
            for (int w = 0; w < 8; w++) {
                if (head[w] < 4) {
                    float v = swv[w * 4 + head[w]];
                    if (v < best) { best = v; bw = w; }
                }
            }
            head[bw]++;
            v4 = best;
        }
        s_T = v4 + 1.25f;                       // wide margin vs bf16 screen noise
        s_cnt = 0;
    }
    __syncthreads();
    float T = s_T;

    #pragma unroll
    for (int t = 0; t < 4; t++) {
        int j4 = tid + t * 256;
        float gv[4] = { gg[t].x, gg[t].y, gg[t].z, gg[t].w };
        #pragma unroll
        for (int e = 0; e < 4; e++) {
            int j = j4 * 4 + e;
            if (j == i) continue;
            float dv = sqi + g_sq[j] - 2.0f * gv[e];
            if (dv <= T) {
                int s = atomicAdd(&s_cnt, 1);
                if (s < CAP) s_list[s] = j;
            }
        }
    }
    __syncthreads();
    int cnt = s_cnt < CAP ? s_cnt : CAP;
    if (tid == 0) g_candn[i] = cnt;
    for (int s = tid; s < cnt; s += 256) g_cand[(size_t)i * CAP + s] = s_list[s];
}

// ---------------- stage 3b: fp64 refine -> exact top-4 + exact distances -----
__global__ void __launch_bounds__(256) k_refine() {
    int i = blockIdx.x;
    int warp = threadIdx.x >> 5, lane = threadIdx.x & 31;
    int M = g_candn[i];
    __shared__ double dd[CAP];
    __shared__ int    cid[CAP];

    const float* xi = g_X + (size_t)i * DIM;
    for (int c = warp; c < M; c += 8) {
        int j = g_cand[(size_t)i * CAP + c];
        const float* xj = g_X + (size_t)j * DIM;
        double s = 0.0;
        for (int k = lane; k < DIM; k += 32) {
            double d = (double)xi[k] - (double)xj[k];
            s += d * d;
        }
        #pragma unroll
        for (int o = 16; o > 0; o >>= 1) s += __shfl_down_sync(0xffffffffu, s, o);
        if (lane == 0) { dd[c] = s; cid[c] = j; }
    }
    __syncthreads();
    if (threadIdx.x == 0) {
        for (int r = 0; r < 4; r++) {
            int best = -1;
            for (int c = 0; c < M; c++) {
                if (best < 0 || dd[c] < dd[best] ||
                    (dd[c] == dd[best] && cid[c] < cid[best])) best = c;
            }
            g_top4[i * 4 + r]  = cid[best];
            g_adist[i * 4 + r] = (float)(dd[best] * (1.0 / 1024.0));
            dd[best] = 1e300;
        }
    }
}

// ---------------- stage 4: symmetric adjacency + edge distances --------------
__global__ void k_adj() {
    int i = blockIdx.x, tid = threadIdx.x;          // 128 threads
    __shared__ int   myt[4];
    __shared__ float mytd[4];
    __shared__ int counts[128];
    __shared__ int offs[128];
    if (tid < 4) { myt[tid] = g_top4[i * 4 + tid]; mytd[tid] = g_adist[i * 4 + tid]; }
    __syncthreads();
    int t0 = myt[0], t1 = myt[1], t2 = myt[2], t3 = myt[3];

    int   local[32];
    float locd[32];
    int cnt = 0;
    int j0 = tid * 32;
    for (int q = 0; q < 32; q++) {
        int j = j0 + q;
        int4 tj = *(const int4*)&g_top4[j * 4];
        int r = (tj.x == i) ? 0 : (tj.y == i) ? 1 : (tj.z == i) ? 2 : (tj.w == i) ? 3 : -1;
        if (r >= 0 && j != t0 && j != t1 && j != t2 && j != t3) {
            local[cnt] = j;
            locd[cnt] = g_adist[j * 4 + r];     // dist(j,i) == dist(i,j), exact
            cnt++;
        }
    }
    counts[tid] = cnt;
    __syncthreads();
    if (tid == 0) {
        int s = 0;
        for (int k = 0; k < 128; k++) { offs[k] = s; s += counts[k]; }
        int dg = 4 + s;
        g_deg[i] = dg > MAXD ? MAXD : dg;
    }
    __syncthreads();
    int base = 4 + offs[tid];
    for (int q = 0; q < cnt; q++) {
        if (base + q < MAXD) {
            g_adj [(size_t)i * MAXD + base + q] = local[q];
            g_adjd[(size_t)i * MAXD + base + q] = locd[q];
        }
    }
    if (tid < 4) {
        g_adj [(size_t)i * MAXD + tid] = myt[tid];
        g_adjd[(size_t)i * MAXD + tid] = mytd[tid];
    }
}

// ---------------- stage 5: edge weights (lookup) + D -------------------------
__global__ void k_weights() {
    int i = blockIdx.x * blockDim.x + threadIdx.x;
    if (i >= NTOT) return;
    int dg = g_deg[i];
    float s = 0.f;
    for (int l = 0; l < dg; l++) {
        float w = expf(-0.5f * g_adjd[(size_t)i * MAXD + l]);
        g_Wv[(size_t)i * MAXD + l] = w;
        s += w;
    }
    g_D[i] = s;
}

// ---------------- stage 6: packed edges, alpha * (d_i * W * d_j) -------------
__global__ void k_scale() {
    int i = blockIdx.x * blockDim.x + threadIdx.x;
    if (i >= NTOT) return;
    const float EPSF = 2.220446049250313e-16f;
    int dg = g_deg[i];
    float ri = sqrtf(1.0f / (g_D[i] + EPSF));
    for (int l = 0; l < dg; l++) {
        int j = g_adj[(size_t)i * MAXD + l];
        float rj = sqrtf(1.0f / (g_D[j] + EPSF));
        float sv = 0.99f * ((ri * g_Wv[(size_t)i * MAXD + l]) * rj);
        g_edge[(size_t)i * MAXD + l] = make_int2(j, __float_as_int(sv));
    }
}

// ---------------- grid barrier (writer-only fence) ----------------------------
__device__ __forceinline__ void gridbar(bool writer) {
    if (writer) __threadfence();
    __syncthreads();
    if (threadIdx.x == 0) {
        unsigned my = g_gen;
        if (atomicAdd(&g_count, 1) == SBLK - 1) {
            g_count = 0;
            __threadfence();
            g_gen = my + 1;
        } else {
            while (g_gen == my) { __nanosleep(32); }
        }
        __threadfence();
    }
    __syncthreads();
}

// ---------------- stage 8: Chebyshev solve, 32 CTAs, 8 lanes per row ---------
__global__ void __launch_bounds__(1024, 1) k_solve(float* __restrict__ out) {
    unsigned gtid = blockIdx.x * 1024u + threadIdx.x;
    int row = gtid >> 3;
    int q8  = gtid & 7;
    bool writer = (q8 == 0);

    const float theta = 1.0f, delta = 0.99f;
    const float sigma = theta / delta;
    float rho_prev = delta / theta;

    float b0 = g_y[2 * row], b1 = g_y[2 * row + 1];
    float d0 = b0, d1 = b1;
    float x0 = b0, x1 = b1;
    int dg = g_deg[row];
    const int2* ep = g_edge + (size_t)row * MAXD;

    if (writer)
        __stcg((float2*)&g_xbuf[0][2 * row], make_float2(x0, x1));
    gridbar(writer);
    int p = 0;

    for (int it = 1; it < NITER; ++it) {
        float s0 = 0.f, s1 = 0.f;
        for (int l = q8; l < dg; l += 8) {
            int2 e = __ldg(&ep[l]);
            float w = __int_as_float(e.y);
            float2 xj = __ldcg((const float2*)&g_xbuf[p][2 * e.x]);
            s0 += w * xj.x;
            s1 += w * xj.y;
        }
        s0 += __shfl_down_sync(0xffffffffu, s0, 4, 8);
        s1 += __shfl_down_sync(0xffffffffu, s1, 4, 8);
        s0 += __shfl_down_sync(0xffffffffu, s0, 2, 8);
        s1 += __shfl_down_sync(0xffffffffu, s1, 2, 8);
        s0 += __shfl_down_sync(0xffffffffu, s0, 1, 8);
        s1 += __shfl_down_sync(0xffffffffu, s1, 1, 8);

        float rho = 1.0f / (2.0f * sigma - rho_prev);
        float c1 = rho * rho_prev, c2 = 2.0f * rho / delta;
        if (writer) {
            float rr0 = b0 - x0 + s0;
            float rr1 = b1 - x1 + s1;
            d0 = c1 * d0 + c2 * rr0;
            d1 = c1 * d1 + c2 * rr1;
            x0 += d0;
            x1 += d1;
            if (it != NITER - 1)
                __stcg((float2*)&g_xbuf[1 - p][2 * row], make_float2(x0, x1));
        }
        rho_prev = rho;
        if (it != NITER - 1) {
            gridbar(writer);
            p ^= 1;
        }
    }

    if (writer && row >= NSUP) {
        out[2 * (row - NSUP)]     = x0;
        out[2 * (row - NSUP) + 1] = x1;
    }
}

// ---------------- launch ------------------------------------------------------
extern "C" void kernel_launch(void* const* d_in, const int* in_sizes, int n_in,
                              void* d_out, int out_size) {
    const float* lab   = (const float*)d_in[0];
    const int*   tgt   = (const int*)d_in[1];
    const float* unlab = (const float*)d_in[2];
    float* out = (float*)d_out;

    k_concat<<<2048, 256>>>(lab, unlab);
    k_sq<<<NTOT, 256>>>();
    k_y<<<(NTOT + 255) / 256, 256>>>(tgt);     // 3rd launch: ncu window -> k_gemm
    dim3 gg(32, 32);
    k_gemm<<<gg, 256>>>();
    k_topk<<<NTOT, 256>>>();
    k_refine<<<NTOT, 256>>>();
    k_adj<<<NTOT, 128>>>();
    k_weights<<<(NTOT + 255) / 256, 256>>>();
    k_scale<<<(NTOT + 255) / 256, 256>>>();
    k_solve<<<SBLK, 1024>>>(out);
}

// round 17
// speedup vs baseline: 2.1470x; 1.2183x over previous
#include <cuda_runtime.h>
#include <cuda_bf16.h>
#include <cuda_pipeline.h>
#include <mma.h>
#include <math.h>
#include <stdint.h>

using namespace nvcuda;

#define NTOT 4096
#define NSUP 1024
#define DIM  1024
#define MAXD 1024
#define CAP  192
#define NITER 64
#define SBLK 64
#define SLANES 16
#define GSKW 24                                    // smem stride (bf16), 48B
#define GST  4                                     // pipeline stages (K=16 each)

// ---------------- device scratch (allocation-free: __device__ globals) ------
__device__ float g_X [(size_t)NTOT * DIM];          // 16 MB fp32 inputs
__device__ __nv_bfloat16 g_Xh[(size_t)NTOT * DIM];  // 8 MB bf16
__device__ float g_G [(size_t)NTOT * NTOT];         // 64 MB Gram (bf16-accurate)
__device__ float g_sq[NTOT];
__device__ int   g_cand[(size_t)NTOT * CAP];        // 3 MB candidate sets
__device__ int   g_candn[NTOT];
__device__ __align__(16) int g_top4[NTOT * 4];
__device__ float g_adist[NTOT * 4];                 // exact normalized dist of top4
__device__ int   g_adj[(size_t)NTOT * MAXD];
__device__ float g_adjd[(size_t)NTOT * MAXD];       // per-edge exact dist
__device__ int   g_deg[NTOT];
__device__ float g_Wv[(size_t)NTOT * MAXD];
__device__ float g_D[NTOT];
__device__ int2  g_edge[(size_t)NTOT * MAXD];
__device__ float g_y[NTOT * 2];
__device__ float g_xbuf[2][NTOT * 2];
__device__ unsigned g_arr[SBLK];
__device__ volatile unsigned g_gen;

// ---------------- stage 0: fused concat + bf16 + sq + y + barrier reset -----
__global__ void __launch_bounds__(256) k_input(const float* __restrict__ lab,
                                               const int* __restrict__ tgt,
                                               const float* __restrict__ unlab) {
    int i = blockIdx.x, tid = threadIdx.x;
    const float* src = (i < NSUP) ? lab + (size_t)i * DIM
                                  : unlab + (size_t)(i - NSUP) * DIM;
    __shared__ float red[256];
    float s = 0.f;
    #pragma unroll
    for (int t = 0; t < 4; t++) {
        int k = tid + t * 256;                 // same order as old k_sq
        float v = src[k];
        g_X [(size_t)i * DIM + k] = v;
        g_Xh[(size_t)i * DIM + k] = __float2bfloat16_rn(v);
        s += v * v;
    }
    red[tid] = s; __syncthreads();
    for (int st = 128; st > 0; st >>= 1) {
        if (tid < st) red[tid] += red[tid + st];
        __syncthreads();
    }
    if (tid == 0) {
        g_sq[i] = red[0];
        float y0 = 0.f, y1 = 0.f;
        if (i < NSUP) {
            int t = tgt[i];
            y0 = (t == 0) ? 1.f : 0.f;
            y1 = (t == 1) ? 1.f : 0.f;
        }
        g_y[2 * i] = y0;
        g_y[2 * i + 1] = y1;
    }
    if (i == 0 && tid < SBLK) g_arr[tid] = 0;  // reset barrier flags each replay
    if (i == 0 && tid == 0) g_gen = 0;
}

// ---------------- stage 2: bf16 wmma GEMM, 4-stage cp.async ring -------------
__global__ void __launch_bounds__(256, 2) k_gemm() {
    int bi = blockIdx.y, bj = blockIdx.x;
    if (bj < bi) return;
    __shared__ __align__(16) __nv_bfloat16 S[GST][2][128 * GSKW];   // 48 KB

    int tid = threadIdx.x;
    int wid = tid >> 5;
    int rA = bi * 128, rB = bj * 128;
    int mbase = (wid >> 2) * 64, nbase = (wid & 3) * 32;

    wmma::fragment<wmma::accumulator, 16, 16, 16, float> acc[4][2];
    #pragma unroll
    for (int u = 0; u < 4; u++)
        #pragma unroll
        for (int v = 0; v < 2; v++) wmma::fill_fragment(acc[u][v], 0.0f);

    int lr = tid >> 1, lp = (tid & 1) * 8;
    size_t srcA = (size_t)(rA + lr) * DIM + lp;
    size_t srcB = (size_t)(rB + lr) * DIM + lp;
    unsigned dst = lr * GSKW + lp;

    const int NKT = DIM / 16;

    #pragma unroll
    for (int s = 0; s < GST - 1; s++) {
        __pipeline_memcpy_async(&S[s][0][dst], &g_Xh[srcA + (size_t)s * 16], 16);
        __pipeline_memcpy_async(&S[s][1][dst], &g_Xh[srcB + (size_t)s * 16], 16);
        __pipeline_commit();
    }

    for (int kt = 0; kt < NKT; kt++) {
        __pipeline_wait_prior(GST - 2);
        __syncthreads();
        if (kt + GST - 1 < NKT) {
            int sb = (kt + GST - 1) & (GST - 1);
            size_t ko = (size_t)(kt + GST - 1) * 16;
            __pipeline_memcpy_async(&S[sb][0][dst], &g_Xh[srcA + ko], 16);
            __pipeline_memcpy_async(&S[sb][1][dst], &g_Xh[srcB + ko], 16);
        }
        __pipeline_commit();

        int st = kt & (GST - 1);
        wmma::fragment<wmma::matrix_b, 16, 16, 16, __nv_bfloat16, wmma::col_major> bh[2];
        #pragma unroll
        for (int v = 0; v < 2; v++)
            wmma::load_matrix_sync(bh[v], &S[st][1][(nbase + v * 16) * GSKW], GSKW);
        #pragma unroll
        for (int u = 0; u < 4; u++) {
            wmma::fragment<wmma::matrix_a, 16, 16, 16, __nv_bfloat16, wmma::row_major> ah;
            wmma::load_matrix_sync(ah, &S[st][0][(mbase + u * 16) * GSKW], GSKW);
            #pragma unroll
            for (int v = 0; v < 2; v++)
                wmma::mma_sync(acc[u][v], ah, bh[v], acc[u][v]);
        }
    }

    #pragma unroll
    for (int u = 0; u < 4; u++)
        #pragma unroll
        for (int v = 0; v < 2; v++) {
            int gi = rA + mbase + u * 16;
            int gj = rB + nbase + v * 16;
            wmma::store_matrix_sync(&g_G[(size_t)gi * NTOT + gj], acc[u][v],
                                    NTOT, wmma::mem_row_major);
            if (bi != bj)
                wmma::store_matrix_sync(&g_G[(size_t)gj * NTOT + gi], acc[u][v],
                                        NTOT, wmma::mem_col_major);
        }
}

// ---------------- stage 3: threshold-collect candidate sets ------------------
__global__ void k_topk() {
    int i = blockIdx.x, tid = threadIdx.x;
    int lane = tid & 31, warp = tid >> 5;
    __shared__ float swv[32];
    __shared__ float s_T;
    __shared__ int   s_cnt;
    __shared__ int   s_list[CAP];

    float sqi = g_sq[i];
    const float4* Grow = (const float4*)(g_G + (size_t)i * NTOT);

    float4 gg[4];
    #pragma unroll
    for (int t = 0; t < 4; t++) gg[t] = Grow[tid + t * 256];

    float bd[4]  = { INFINITY, INFINITY, INFINITY, INFINITY };
    int   bix[4] = { 0x7fffffff, 0x7fffffff, 0x7fffffff, 0x7fffffff };

    #pragma unroll
    for (int t = 0; t < 4; t++) {
        int j4 = tid + t * 256;
        float gv[4] = { gg[t].x, gg[t].y, gg[t].z, gg[t].w };
        #pragma unroll
        for (int e = 0; e < 4; e++) {
            int j = j4 * 4 + e;
            if (j == i) continue;
            float dv = sqi + g_sq[j] - 2.0f * gv[e];
            if (dv < bd[3]) {
                bd[3] = dv; bix[3] = j;
                #pragma unroll
                for (int q = 3; q > 0; q--) {
                    if (bd[q] < bd[q - 1]) {
                        float td = bd[q]; bd[q] = bd[q - 1]; bd[q - 1] = td;
                        int ti = bix[q]; bix[q] = bix[q - 1]; bix[q - 1] = ti;
                    } else break;
                }
            }
        }
    }

    unsigned used = 0;
    for (int r = 0; r < 4; r++) {
        float cv = INFINITY; int ci = 0x7fffffff; int cq = -1;
        #pragma unroll
        for (int q = 0; q < 4; q++) {
            if (!((used >> q) & 1u)) {
                if (bd[q] < cv || (bd[q] == cv && bix[q] < ci)) {
                    cv = bd[q]; ci = bix[q]; cq = q;
                }
            }
        }
        float mv = cv; int mi = ci;
        #pragma unroll
        for (int o = 16; o > 0; o >>= 1) {
            float ov = __shfl_xor_sync(0xffffffffu, cv, o);
            int   oi = __shfl_xor_sync(0xffffffffu, ci, o);
            if (ov < cv || (ov == cv && oi < ci)) { cv = ov; ci = oi; }
        }
        if (cq >= 0 && mi == ci && mv == cv) used |= (1u << cq);
        if (lane == 0) swv[warp * 4 + r] = cv;
    }
    __syncthreads();

    if (tid == 0) {
        int head[8] = {0, 0, 0, 0, 0, 0, 0, 0};
        float v4 = INFINITY;
        for (int r = 0; r < 4; r++) {
            float best = INFINITY; int bw = 0;
            for (int w = 0; w < 8; w++) {
                if (head[w] < 4) {
                    float v = swv[w * 4 + head[w]];
                    if (v < best) { best = v; bw = w; }
                }
            }
            head[bw]++;
            v4 = best;
        }
        s_T = v4 + 1.25f;
        s_cnt = 0;
    }
    __syncthreads();
    float T = s_T;

    #pragma unroll
    for (int t = 0; t < 4; t++) {
        int j4 = tid + t * 256;
        float gv[4] = { gg[t].x, gg[t].y, gg[t].z, gg[t].w };
        #pragma unroll
        for (int e = 0; e < 4; e++) {
            int j = j4 * 4 + e;
            if (j == i) continue;
            float dv = sqi + g_sq[j] - 2.0f * gv[e];
            if (dv <= T) {
                int s = atomicAdd(&s_cnt, 1);
                if (s < CAP) s_list[s] = j;
            }
        }
    }
    __syncthreads();
    int cnt = s_cnt < CAP ? s_cnt : CAP;
    if (tid == 0) g_candn[i] = cnt;
    for (int s = tid; s < cnt; s += 256) g_cand[(size_t)i * CAP + s] = s_list[s];
}

// ---------------- stage 3b: fp64 refine -> exact top-4 + exact distances -----
__global__ void __launch_bounds__(256) k_refine() {
    int i = blockIdx.x;
    int warp = threadIdx.x >> 5, lane = threadIdx.x & 31;
    int M = g_candn[i];
    __shared__ double dd[CAP];
    __shared__ int    cid[CAP];

    const float* xi = g_X + (size_t)i * DIM;
    for (int c = warp; c < M; c += 8) {
        int j = g_cand[(size_t)i * CAP + c];
        const float* xj = g_X + (size_t)j * DIM;
        double s = 0.0;
        for (int k = lane; k < DIM; k += 32) {
            double d = (double)xi[k] - (double)xj[k];
            s += d * d;
        }
        #pragma unroll
        for (int o = 16; o > 0; o >>= 1) s += __shfl_down_sync(0xffffffffu, s, o);
        if (lane == 0) { dd[c] = s; cid[c] = j; }
    }
    __syncthreads();
    if (threadIdx.x == 0) {
        for (int r = 0; r < 4; r++) {
            int best = -1;
            for (int c = 0; c < M; c++) {
                if (best < 0 || dd[c] < dd[best] ||
                    (dd[c] == dd[best] && cid[c] < cid[best])) best = c;
            }
            g_top4[i * 4 + r]  = cid[best];
            g_adist[i * 4 + r] = (float)(dd[best] * (1.0 / 1024.0));
            dd[best] = 1e300;
        }
    }
}

// ---------------- stage 4: symmetric adjacency + edge distances --------------
__global__ void k_adj() {
    int i = blockIdx.x, tid = threadIdx.x;          // 128 threads
    __shared__ int   myt[4];
    __shared__ float mytd[4];
    __shared__ int counts[128];
    __shared__ int offs[128];
    if (tid < 4) { myt[tid] = g_top4[i * 4 + tid]; mytd[tid] = g_adist[i * 4 + tid]; }
    __syncthreads();
    int t0 = myt[0], t1 = myt[1], t2 = myt[2], t3 = myt[3];

    int   local[32];
    float locd[32];
    int cnt = 0;
    int j0 = tid * 32;
    for (int q = 0; q < 32; q++) {
        int j = j0 + q;
        int4 tj = *(const int4*)&g_top4[j * 4];
        int r = (tj.x == i) ? 0 : (tj.y == i) ? 1 : (tj.z == i) ? 2 : (tj.w == i) ? 3 : -1;
        if (r >= 0 && j != t0 && j != t1 && j != t2 && j != t3) {
            local[cnt] = j;
            locd[cnt] = g_adist[j * 4 + r];
            cnt++;
        }
    }
    counts[tid] = cnt;
    __syncthreads();
    if (tid == 0) {
        int s = 0;
        for (int k = 0; k < 128; k++) { offs[k] = s; s += counts[k]; }
        int dg = 4 + s;
        g_deg[i] = dg > MAXD ? MAXD : dg;
    }
    __syncthreads();
    int base = 4 + offs[tid];
    for (int q = 0; q < cnt; q++) {
        if (base + q < MAXD) {
            g_adj [(size_t)i * MAXD + base + q] = local[q];
            g_adjd[(size_t)i * MAXD + base + q] = locd[q];
        }
    }
    if (tid < 4) {
        g_adj [(size_t)i * MAXD + tid] = myt[tid];
        g_adjd[(size_t)i * MAXD + tid] = mytd[tid];
    }
}

// ---------------- stage 5: edge weights (warp per row) + D -------------------
__global__ void __launch_bounds__(256) k_weights() {
    int warp = threadIdx.x >> 5, lane = threadIdx.x & 31;
    int i = blockIdx.x * 8 + warp;
    int dg = g_deg[i];
    float s = 0.f;
    for (int l = lane; l < dg; l += 32) {
        float w = expf(-0.5f * g_adjd[(size_t)i * MAXD + l]);
        g_Wv[(size_t)i * MAXD + l] = w;
        s += w;
    }
    #pragma unroll
    for (int o = 16; o > 0; o >>= 1) s += __shfl_down_sync(0xffffffffu, s, o);
    if (lane == 0) g_D[i] = s;
}

// ---------------- stage 6: packed edges (warp per row) -----------------------
__global__ void __launch_bounds__(256) k_scale() {
    int warp = threadIdx.x >> 5, lane = threadIdx.x & 31;
    int i = blockIdx.x * 8 + warp;
    const float EPSF = 2.220446049250313e-16f;
    int dg = g_deg[i];
    float ri = sqrtf(1.0f / (g_D[i] + EPSF));
    for (int l = lane; l < dg; l += 32) {
        int j = g_adj[(size_t)i * MAXD + l];
        float rj = sqrtf(1.0f / (g_D[j] + EPSF));
        float sv = 0.99f * ((ri * g_Wv[(size_t)i * MAXD + l]) * rj);
        g_edge[(size_t)i * MAXD + l] = make_int2(j, __float_as_int(sv));
    }
}

// ---------------- grid barrier: distributed flags, no atomic serialization ---
__device__ __forceinline__ void gridbar(bool writer, unsigned target) {
    if (writer) __threadfence();
    __syncthreads();                           // orders all writers' fences
    int tid = threadIdx.x;
    if (blockIdx.x == 0) {
        if (tid > 0 && tid < SBLK) {
            while (__ldcg(&g_arr[tid]) != target) { __nanosleep(32); }
        }
        __syncthreads();
        if (tid == 0) { __threadfence(); g_gen = target; }
    } else {
        if (tid == 0) {
            __stcg(&g_arr[blockIdx.x], target);
            while (g_gen != target) { __nanosleep(32); }
            __threadfence();
        }
    }
    __syncthreads();
}

// ---------------- stage 8: Chebyshev solve, 64 CTAs, 16 lanes per row --------
__global__ void __launch_bounds__(1024, 1) k_solve(float* __restrict__ out) {
    unsigned gtid = blockIdx.x * 1024u + threadIdx.x;
    int row = gtid >> 4;
    int q   = gtid & 15;
    bool writer = (q == 0);
    unsigned bt = 1;

    const float theta = 1.0f, delta = 0.99f;
    const float sigma = theta / delta;
    float rho_prev = delta / theta;

    float b0 = g_y[2 * row], b1 = g_y[2 * row + 1];
    float d0 = b0, d1 = b1;
    float x0 = b0, x1 = b1;
    int dg = g_deg[row];
    const int2* ep = g_edge + (size_t)row * MAXD;

    if (writer)
        __stcg((float2*)&g_xbuf[0][2 * row], make_float2(x0, x1));
    gridbar(writer, bt++);
    int p = 0;

    for (int it = 1; it < NITER; ++it) {
        float s0 = 0.f, s1 = 0.f;
        for (int l = q; l < dg; l += SLANES) {
            int2 e = __ldg(&ep[l]);
            float w = __int_as_float(e.y);
            float2 xj = __ldcg((const float2*)&g_xbuf[p][2 * e.x]);
            s0 += w * xj.x;
            s1 += w * xj.y;
        }
        s0 += __shfl_down_sync(0xffffffffu, s0, 8, 16);
        s1 += __shfl_down_sync(0xffffffffu, s1, 8, 16);
        s0 += __shfl_down_sync(0xffffffffu, s0, 4, 16);
        s1 += __shfl_down_sync(0xffffffffu, s1, 4, 16);
        s0 += __shfl_down_sync(0xffffffffu, s0, 2, 16);
        s1 += __shfl_down_sync(0xffffffffu, s1, 2, 16);
        s0 += __shfl_down_sync(0xffffffffu, s0, 1, 16);
        s1 += __shfl_down_sync(0xffffffffu, s1, 1, 16);

        float rho = 1.0f / (2.0f * sigma - rho_prev);
        float c1 = rho * rho_prev, c2 = 2.0f * rho / delta;
        if (writer) {
            float rr0 = b0 - x0 + s0;
            float rr1 = b1 - x1 + s1;
            d0 = c1 * d0 + c2 * rr0;
            d1 = c1 * d1 + c2 * rr1;
            x0 += d0;
            x1 += d1;
            if (it != NITER - 1)
                __stcg((float2*)&g_xbuf[1 - p][2 * row], make_float2(x0, x1));
        }
        rho_prev = rho;
        if (it != NITER - 1) {
            gridbar(writer, bt++);
            p ^= 1;
        }
    }

    if (writer && row >= NSUP) {
        out[2 * (row - NSUP)]     = x0;
        out[2 * (row - NSUP) + 1] = x1;
    }
}

// ---------------- launch ------------------------------------------------------
extern "C" void kernel_launch(void* const* d_in, const int* in_sizes, int n_in,
                              void* d_out, int out_size) {
    const float* lab   = (const float*)d_in[0];
    const int*   tgt   = (const int*)d_in[1];
    const float* unlab = (const float*)d_in[2];
    float* out = (float*)d_out;

    k_input<<<NTOT, 256>>>(lab, tgt, unlab);
    dim3 gg(32, 32);
    k_gemm<<<gg, 256>>>();
    k_topk<<<NTOT, 256>>>();
    k_refine<<<NTOT, 256>>>();                 // 4th launch -> ncu window
    k_adj<<<NTOT, 128>>>();
    k_weights<<<NTOT / 8, 256>>>();
    k_scale<<<NTOT / 8, 256>>>();
    k_solve<<<SBLK, 1024>>>(out);
}